// round 17
// baseline (speedup 1.0000x reference)
#include <cuda_runtime.h>
#include <math.h>

#define BB 8
#define DD 512
#define NHH 8
#define HDD 64
#define HH 2048
#define NLL 2
#define VV 32000
#define SMAX 64
#define EPSL 1e-5f
#define NB 128
#define NT 512
#define SMEMB (BB * HH * 4 + 512)   // 64KB staging + scratch

typedef unsigned long long ull;

__device__ float g_pe[SMAX*DD];
__device__ float g_x[BB*DD];
__device__ float g_x2[BB*DD];
__device__ float g_q[BB*DD];
__device__ float g_pp[BB*NHH*DD];       // per-head projection partials
__device__ float g_hbuf[BB*HH];
__device__ float g_f2[BB*DD];
__device__ float g_kc[NLL*BB*NHH*SMAX*HDD];
__device__ float g_vc[NLL*BB*NHH*SMAX*HDD];
__device__ float g_cavec[NLL*BB*DD];
__device__ ull   g_amax[2*16*BB];       // parity x 16 shadow slots x batch
__device__ unsigned g_cnt;              // monotonic arrival counter (never reset)
__device__ unsigned g_flags[32*64];     // release flags, 256B apart (monotonic)

__device__ __forceinline__ float wred(float v) {
    v += __shfl_xor_sync(0xffffffffu, v, 16);
    v += __shfl_xor_sync(0xffffffffu, v, 8);
    v += __shfl_xor_sync(0xffffffffu, v, 4);
    v += __shfl_xor_sync(0xffffffffu, v, 2);
    v += __shfl_xor_sync(0xffffffffu, v, 1);
    return v;
}

// Grid barrier (R11/R14-proven, unchanged).
__device__ __forceinline__ void gsync(unsigned &gen, int bx) {
    __syncthreads();
    if (threadIdx.x == 0) {
        unsigned target = gen + 1;
        asm volatile("fence.acq_rel.gpu;" ::: "memory");          // release
        if (atomicAdd(&g_cnt, 1u) == NB * target - 1u) {
            asm volatile("fence.acq_rel.gpu;" ::: "memory");
            #pragma unroll
            for (int i = 0; i < 32; i++)
                asm volatile("st.relaxed.gpu.global.u32 [%0], %1;"
                             :: "l"(&g_flags[i * 64]), "r"(target) : "memory");
        } else {
            unsigned cur;
            unsigned* fl = &g_flags[(bx & 31) * 64];
            do {
                asm volatile("ld.relaxed.gpu.global.u32 %0, [%1];"
                             : "=r"(cur) : "l"(fl));
            } while ((int)(cur - target) < 0);                    // wrap-safe
        }
        asm volatile("fence.acq_rel.gpu;" ::: "memory");          // acquire
    }
    gen = gen + 1;
    __syncthreads();
}

__device__ __forceinline__ ull ffma2(ull a, ull b, ull c) {
    ull d;
    asm("fma.rn.f32x2 %0, %1, %2, %3;" : "=l"(d) : "l"(a), "l"(b), "l"(c));
    return d;
}
__device__ __forceinline__ float f2sum(ull a) {
    return __uint_as_float((unsigned)a) + __uint_as_float((unsigned)(a >> 32));
}

__device__ __forceinline__ void lnorm(float4* y, const float* gam, const float* bet, int lane) {
    float s = 0.f;
    #pragma unroll
    for (int k = 0; k < 4; k++) s += y[k].x + y[k].y + y[k].z + y[k].w;
    float m = wred(s) * (1.f / DD);
    float v = 0.f;
    #pragma unroll
    for (int k = 0; k < 4; k++) {
        float a = y[k].x - m, b = y[k].y - m, c = y[k].z - m, d = y[k].w - m;
        v += a * a + b * b + c * c + d * d;
    }
    v = wred(v) * (1.f / DD);
    float r = 1.f / sqrtf(v + EPSL);
    #pragma unroll
    for (int k = 0; k < 4; k++) {
        float4 g = ((const float4*)gam)[lane + 32 * k];
        float4 b4 = ((const float4*)bet)[lane + 32 * k];
        y[k].x = (y[k].x - m) * r * g.x + b4.x;
        y[k].y = (y[k].y - m) * r * g.y + b4.y;
        y[k].z = (y[k].z - m) * r * g.z + b4.z;
        y[k].w = (y[k].w - m) * r * g.w + b4.w;
    }
}

__device__ __forceinline__ void dot8(const float* __restrict__ w, const float* xs,
                                     int lane, float* acc) {
    const float4* w4 = (const float4*)w;
    const float4* x4 = (const float4*)xs;
    #pragma unroll
    for (int k = 0; k < 4; k++) {
        float4 ww = w4[lane + 32 * k];
        #pragma unroll
        for (int b = 0; b < 8; b++) {
            float4 h = x4[b * 128 + lane + 32 * k];
            acc[b] += ww.x * h.x + ww.y * h.y + ww.z * h.z + ww.w * h.w;
        }
    }
}

// butterfly-merge: lane L ends with the full sum of a[L&7]
__device__ __forceinline__ float red8m(float* a, int lane) {
    #pragma unroll
    for (int s = 0; s < 3; s++) {
        int off = 1 << s, n = 8 >> (s + 1);
        #pragma unroll
        for (int i = 0; i < n; i++) {
            float x = (lane & off) ? a[2 * i] : a[2 * i + 1];
            float rc = __shfl_xor_sync(0xffffffffu, x, off);
            a[i] = ((lane & off) ? a[2 * i + 1] : a[2 * i]) + rc;
        }
    }
    float v = a[0];
    v += __shfl_xor_sync(0xffffffffu, v, 8);
    v += __shfl_xor_sync(0xffffffffu, v, 16);
    return v;
}
__device__ __forceinline__ float red4m(float* a, int lane) {
    #pragma unroll
    for (int s = 0; s < 2; s++) {
        int off = 1 << s, n = 4 >> (s + 1);
        #pragma unroll
        for (int i = 0; i < n; i++) {
            float x = (lane & off) ? a[2 * i] : a[2 * i + 1];
            float rc = __shfl_xor_sync(0xffffffffu, x, off);
            a[i] = ((lane & off) ? a[2 * i + 1] : a[2 * i]) + rc;
        }
    }
    float v = a[0];
    v += __shfl_xor_sync(0xffffffffu, v, 4);
    v += __shfl_xor_sync(0xffffffffu, v, 8);
    v += __shfl_xor_sync(0xffffffffu, v, 16);
    return v;
}

__device__ __forceinline__ int amax_tok(ull key) {
    return (int)(0xFFFFFFFFu - (unsigned)(key & 0xFFFFFFFFull));
}

// max over 16 shadow slots for (parity parX, batch b); result on ALL lanes
__device__ __forceinline__ ull amax_slot_max(int parX, int b, int lane) {
    ull k = (lane < 16) ? g_amax[parX * 128 + lane * 8 + b] : 0ull;
    #pragma unroll
    for (int off = 1; off <= 8; off <<= 1) {
        ull o = __shfl_xor_sync(0xffffffffu, k, off);
        if (o > k) k = o;
    }
    ull o = __shfl_xor_sync(0xffffffffu, k, 16);
    if (o > k) k = o;
    return k;
}

__global__ void __launch_bounds__(NT)
kmain(const float* __restrict__ memory, const float* __restrict__ emb,
      const float* __restrict__ sa_in_w, const float* __restrict__ sa_in_b,
      const float* __restrict__ sa_out_w, const float* __restrict__ sa_out_b,
      const float* __restrict__ ca_in_w, const float* __restrict__ ca_in_b,
      const float* __restrict__ ca_out_w, const float* __restrict__ ca_out_b,
      const float* __restrict__ ff1_w, const float* __restrict__ ff1_b,
      const float* __restrict__ ff2_w, const float* __restrict__ ff2_b,
      const float* __restrict__ ln1_g, const float* __restrict__ ln1_b,
      const float* __restrict__ ln2_g, const float* __restrict__ ln2_b,
      const float* __restrict__ ln3_g, const float* __restrict__ ln3_b,
      const float* __restrict__ out_w, const float* __restrict__ out_b,
      float* __restrict__ tok_out, float* __restrict__ log_out, int L, int wt)
{
    extern __shared__ __align__(16) float xs[];   // 64KB dynamic staging
    __shared__ ull sbest[BB];
    int tid = threadIdx.x, lane = tid & 31, warp = tid >> 5;  // 16 warps
    int bx = blockIdx.x, gw = bx * 16 + warp, gtid = bx * NT + tid;

    // launch-idempotent barrier init: read the quiescent generation
    unsigned gen;
    asm volatile("ld.relaxed.gpu.global.u32 %0, [%1];"
                 : "=r"(gen) : "l"(&g_flags[(bx & 31) * 64]));

    // ---- setup: PE table, argmax slots (both parities) ----
    for (int i = gtid; i < SMAX * DD; i += NB * NT) {
        int d = i & 511;
        double dv = exp((double)(d & ~1) * (-9.210340371976184 / 512.0));
        float arg = (float)(i >> 9) * (float)dv;
        g_pe[i] = (d & 1) ? cosf(arg) : sinf(arg);
    }
    if (gtid < 2 * 16 * BB) g_amax[gtid] = 0ull;
    gsync(gen, bx);

    // ---- cross-attn constant (Sk=1 => softmax==1) on blocks 0..15 ----
    if (bx < NLL * BB) {
        int l = bx >> 3, b = bx & 7;
        const float4* m4 = (const float4*)(memory + b * DD);
        for (int j = warp; j < DD; j += 16) {
            const float4* w4 = (const float4*)(ca_in_w + ((size_t)l * 3 * DD + 2 * DD + j) * DD);
            float acc = 0.f;
            #pragma unroll
            for (int k = 0; k < 4; k++) {
                float4 w = w4[lane + 32 * k], x = m4[lane + 32 * k];
                acc += w.x * x.x + w.y * x.y + w.z * x.z + w.w * x.w;
            }
            acc = wred(acc);
            if (lane == 0) xs[j] = acc + ca_in_b[l * 3 * DD + 2 * DD + j];
        }
        __syncthreads();
        for (int j = warp; j < DD; j += 16) {
            const float4* w4 = (const float4*)(ca_out_w + ((size_t)l * DD + j) * DD);
            const float4* v4 = (const float4*)xs;
            float acc = 0.f;
            #pragma unroll
            for (int k = 0; k < 4; k++) {
                float4 w = w4[lane + 32 * k], x = v4[lane + 32 * k];
                acc += w.x * x.x + w.y * x.y + w.z * x.z + w.w * x.w;
            }
            acc = wred(acc);
            if (lane == 0) g_cavec[(l * BB + b) * DD + j] = acc + ca_out_b[l * DD + j];
        }
    }
    gsync(gen, bx);

    for (int t = 0; t < L; t++) {
        int par = t & 1;
        for (int l = 0; l < NLL; l++) {
            // ---- QKV: 96 blocks x 16 warps = 1536 warps x exactly 1 row ----
            if (bx < 96) {
                if (warp < BB) {
                    int b = warp;
                    float4 y[4];
                    if (l == 0) {
                        int tok;
                        if (t == 0) {
                            tok = 1;
                        } else {
                            ull key = amax_slot_max(1 - par, b, lane);
                            tok = amax_tok(key);
                            if (bx == 0 && wt && lane == 0)
                                tok_out[b * L + (t - 1)] = (float)tok;
                        }
                        const float4* e4 = (const float4*)(emb + (size_t)tok * DD);
                        const float4* p4 = (const float4*)(g_pe + t * DD);
                        #pragma unroll
                        for (int k = 0; k < 4; k++) {
                            float4 e = e4[lane + 32 * k], p = p4[lane + 32 * k];
                            y[k] = make_float4(e.x + p.x, e.y + p.y, e.z + p.z, e.w + p.w);
                        }
                    } else {
                        #pragma unroll
                        for (int k = 0; k < 4; k++) {
                            float4 a = ((const float4*)(g_x2 + b * DD))[lane + 32 * k];
                            float4 c = ((const float4*)(g_f2 + b * DD))[lane + 32 * k];
                            y[k] = make_float4(a.x + c.x, a.y + c.y, a.z + c.z, a.w + c.w);
                        }
                        lnorm(y, ln3_g + (l - 1) * DD, ln3_b + (l - 1) * DD, lane);
                    }
                    #pragma unroll
                    for (int k = 0; k < 4; k++) {
                        ((float4*)xs)[b * 128 + lane + 32 * k] = y[k];
                        if (bx == 0) ((float4*)g_x)[b * 128 + lane + 32 * k] = y[k];
                    }
                }
                if (l == 0 && bx == 0 && tid < 16 * BB)
                    g_amax[par * 128 + tid] = 0ull;   // reset current-parity slots
                __syncthreads();
                {
                    int j = gw;                               // exactly 1536 rows
                    float acc[8] = {0, 0, 0, 0, 0, 0, 0, 0};
                    dot8(sa_in_w + ((size_t)l * 3 * DD + j) * DD, xs, lane, acc);
                    float val = red8m(acc, lane);
                    if (lane < 8) {
                        val += sa_in_b[l * 3 * DD + j];
                        if (j < DD) g_q[lane * DD + j] = val;
                        else if (j < 2 * DD) {
                            int h = (j - DD) >> 6, d = (j - DD) & 63;
                            g_kc[(((l * BB + lane) * NHH + h) * SMAX + t) * HDD + d] = val;
                        } else {
                            int h = (j - 2 * DD) >> 6, d = (j - 2 * DD) & 63;
                            g_vc[(((l * BB + lane) * NHH + h) * SMAX + t) * HDD + d] = val;
                        }
                    }
                }
            }
            gsync(gen, bx);

            // ---- self-attn + proj partial: 128 blocks, 2 per (b,h) ----
            {
                int pr = bx & 1;            // which 256-dim half of proj
                int bh = bx >> 1;
                int b = bh >> 3, h = bh & 7, n = t + 1;
                float* psh = xs;            // 64 probs (zero-padded)
                float* osh = xs + 64;       // 16 x 64 partial PV outputs
                float* ohd = xs + 1216;     // 64 final head output
                const float* kb = g_kc + (size_t)(((l * BB + b) * NHH + h) * SMAX) * HDD;
                const float* vb = g_vc + (size_t)(((l * BB + b) * NHH + h) * SMAX) * HDD;
                if (warp == 0) {
                    const float4* q4 = (const float4*)(g_q + b * DD + h * HDD);
                    float s0 = -1e30f, s1 = -1e30f;
                    if (lane < n) {
                        const float4* k4 = (const float4*)(kb + (size_t)lane * HDD);
                        float a = 0.f;
                        #pragma unroll
                        for (int k = 0; k < 16; k++) {
                            float4 kk = k4[k], qq = q4[k];
                            a += kk.x * qq.x + kk.y * qq.y + kk.z * qq.z + kk.w * qq.w;
                        }
                        s0 = a * 0.125f;
                    }
                    if (lane + 32 < n) {
                        const float4* k4 = (const float4*)(kb + (size_t)(lane + 32) * HDD);
                        float a = 0.f;
                        #pragma unroll
                        for (int k = 0; k < 16; k++) {
                            float4 kk = k4[k], qq = q4[k];
                            a += kk.x * qq.x + kk.y * qq.y + kk.z * qq.z + kk.w * qq.w;
                        }
                        s1 = a * 0.125f;
                    }
                    float m = fmaxf(s0, s1);
                    #pragma unroll
                    for (int off = 16; off; off >>= 1)
                        m = fmaxf(m, __shfl_xor_sync(0xffffffffu, m, off));
                    float p0 = (lane < n) ? expf(s0 - m) : 0.f;
                    float p1 = (lane + 32 < n) ? expf(s1 - m) : 0.f;
                    float sum = wred(p0 + p1);
                    psh[lane] = p0;
                    psh[lane + 32] = p1;
                    if (lane == 0) xs[1312] = sum;
                }
                __syncthreads();
                {   // 16 warps split PV (probs zero beyond n)
                    float o0 = 0.f, o1 = 0.f;
                    #pragma unroll
                    for (int i = 0; i < 4; i++) {
                        int j = warp + i * 16;
                        float p = psh[j];
                        o0 += p * vb[(size_t)j * HDD + lane];
                        o1 += p * vb[(size_t)j * HDD + lane + 32];
                    }
                    osh[warp * 64 + lane] = o0;
                    osh[warp * 64 + lane + 32] = o1;
                }
                __syncthreads();
                if (warp == 0) {
                    float inv = 1.f / xs[1312];
                    float a0 = 0.f, a1 = 0.f;
                    #pragma unroll
                    for (int w = 0; w < 16; w++) {
                        a0 += osh[w * 64 + lane];
                        a1 += osh[w * 64 + lane + 32];
                    }
                    ohd[lane] = a0 * inv;
                    ohd[lane + 32] = a1 * inv;
                }
                __syncthreads();
                // rank-64 projection partial: this block's 256-dim half (warps 0..7)
                if (warp < 8) {
                    int dd = pr * 256 + warp * 32 + lane;   // 1 dim per thread
                    const float4* w4 = (const float4*)(sa_out_w
                        + ((size_t)l * DD + dd) * DD + h * HDD);
                    const float4* o4 = (const float4*)ohd;  // broadcast
                    float acc = 0.f;
                    #pragma unroll
                    for (int k = 0; k < 16; k++) {
                        float4 w = w4[k], o = o4[k];
                        acc += w.x * o.x + w.y * o.y + w.z * o.z + w.w * o.w;
                    }
                    g_pp[((size_t)b * NHH + h) * DD + dd] = acc;
                }
            }
            gsync(gen, bx);

            // ---- LN1(x + Σ_h pp + out_b) -> +cavec -> LN2 -> FFN1 (1 row/warp) ----
            {
                if (warp < BB) {
                    int b = warp;
                    float4 y[4];
                    #pragma unroll
                    for (int k = 0; k < 4; k++) {
                        float4 a = ((const float4*)(g_x + b * DD))[lane + 32 * k];
                        float4 s = ((const float4*)(sa_out_b + l * DD))[lane + 32 * k];
                        y[k] = make_float4(a.x + s.x, a.y + s.y, a.z + s.z, a.w + s.w);
                        #pragma unroll
                        for (int h = 0; h < NHH; h++) {
                            float4 p = ((const float4*)(g_pp + ((size_t)b * NHH + h) * DD))[lane + 32 * k];
                            y[k].x += p.x; y[k].y += p.y; y[k].z += p.z; y[k].w += p.w;
                        }
                    }
                    lnorm(y, ln1_g + l * DD, ln1_b + l * DD, lane);
                    #pragma unroll
                    for (int k = 0; k < 4; k++) {
                        float4 c = ((const float4*)(g_cavec + (l * BB + b) * DD))[lane + 32 * k];
                        y[k].x += c.x; y[k].y += c.y; y[k].z += c.z; y[k].w += c.w;
                    }
                    lnorm(y, ln2_g + l * DD, ln2_b + l * DD, lane);
                    #pragma unroll
                    for (int k = 0; k < 4; k++) {
                        ((float4*)xs)[b * 128 + lane + 32 * k] = y[k];
                        if (bx == 0) ((float4*)g_x2)[b * 128 + lane + 32 * k] = y[k];
                    }
                }
                __syncthreads();
                {
                    int j = gw;                               // exactly 2048 rows
                    float acc[8] = {0, 0, 0, 0, 0, 0, 0, 0};
                    dot8(ff1_w + ((size_t)l * HH + j) * DD, xs, lane, acc);
                    float val = red8m(acc, lane);
                    if (lane < 8)
                        g_hbuf[lane * HH + j] = fmaxf(val + ff1_b[l * HH + j], 0.f);
                }
            }
            gsync(gen, bx);

            // ---- FFN2: both halves staged (64KB), 1024 tasks over 2048 warps ----
            {
                for (int i = tid; i < BB * HH / 4; i += NT)
                    ((float4*)xs)[i] = ((const float4*)g_hbuf)[i];
                __syncthreads();
                if (gw < 1024) {
                    int grp = gw >> 9;                 // batch group 0..1
                    int j = gw & 511;                  // output dim
                    const float4* w4 = (const float4*)(ff2_w + ((size_t)l * DD + j) * HH);
                    const float4* x4 = (const float4*)xs;
                    float acc[4] = {0, 0, 0, 0};
                    #pragma unroll 4
                    for (int k = 0; k < 16; k++) {
                        float4 w = w4[lane + 32 * k];
                        #pragma unroll
                        for (int b = 0; b < 4; b++) {
                            float4 h = x4[grp * 2048 + b * 512 + lane + 32 * k];
                            acc[b] += w.x * h.x + w.y * h.y + w.z * h.z + w.w * h.w;
                        }
                    }
                    float val = red4m(acc, lane);
                    if (lane < 4)
                        g_f2[(grp * 4 + lane) * DD + j] = val + ff2_b[l * DD + j];
                }
            }
            gsync(gen, bx);
        } // layers

        // ---- logits: 125 blocks x 16 warps = 2000 warps x 8 groups x 2 rows ----
        if (bx < 125) {
            if (warp < BB) {
                int b = warp;
                float4 y[4];
                #pragma unroll
                for (int k = 0; k < 4; k++) {
                    float4 a = ((const float4*)(g_x2 + b * DD))[lane + 32 * k];
                    float4 c = ((const float4*)(g_f2 + b * DD))[lane + 32 * k];
                    y[k] = make_float4(a.x + c.x, a.y + c.y, a.z + c.z, a.w + c.w);
                }
                lnorm(y, ln3_g + (NLL - 1) * DD, ln3_b + (NLL - 1) * DD, lane);
                #pragma unroll
                for (int k = 0; k < 4; k++)
                    ((float4*)xs)[b * 128 + lane + 32 * k] = y[k];
            }
            if (tid < BB) sbest[tid] = 0ull;
            __syncthreads();

            const ulonglong2* hsu = (const ulonglong2*)xs;
            int myb = lane & 7, myr = (lane >> 3) & 1;
            ull bestk = 0ull;
            #pragma unroll 1
            for (int g = 0; g < 8; g++) {
                int v0 = (gw * 8 + g) * 2;
                const ulonglong2* wu = (const ulonglong2*)(out_w + (size_t)v0 * DD);
                ull acc[2][8];
                #pragma unroll
                for (int r = 0; r < 2; r++)
                    #pragma unroll
                    for (int bb = 0; bb < 8; bb++) acc[r][bb] = 0ull;
                #pragma unroll
                for (int k = 0; k < 4; k++) {
                    ulonglong2 h[8];
                    #pragma unroll
                    for (int bb = 0; bb < 8; bb++) h[bb] = hsu[bb * 128 + lane + 32 * k];
                    #pragma unroll
                    for (int r = 0; r < 2; r++) {
                        ulonglong2 w = wu[r * 128 + lane + 32 * k];
                        #pragma unroll
                        for (int bb = 0; bb < 8; bb++) {
                            acc[r][bb] = ffma2(w.x, h[bb].x, acc[r][bb]);
                            acc[r][bb] = ffma2(w.y, h[bb].y, acc[r][bb]);
                        }
                    }
                }
                float a[16];
                #pragma unroll
                for (int r = 0; r < 2; r++)
                    #pragma unroll
                    for (int bb = 0; bb < 8; bb++) a[r * 8 + bb] = f2sum(acc[r][bb]);
                // merge: lane L (mod 16) ends with sum-half of a[L&15]
                #pragma unroll
                for (int s = 0; s < 4; s++) {
                    int off = 1 << s, n = 16 >> (s + 1);
                    #pragma unroll
                    for (int i = 0; i < n; i++) {
                        float x = (lane & off) ? a[2 * i] : a[2 * i + 1];
                        float rc = __shfl_xor_sync(0xffffffffu, x, off);
                        a[i] = ((lane & off) ? a[2 * i + 1] : a[2 * i]) + rc;
                    }
                }
                float v16 = a[0] + __shfl_xor_sync(0xffffffffu, a[0], 16);
                if (lane < 16) {
                    int v = v0 + myr;
                    float val = v16 + out_b[v];
                    log_out[((size_t)myb * L + t) * VV + v] = val;
                    unsigned u = __float_as_uint(val);
                    u = (u & 0x80000000u) ? ~u : (u | 0x80000000u);
                    ull key = ((ull)u << 32) | (unsigned)(0xFFFFFFFFu - (unsigned)v);
                    if (key > bestk) bestk = key;
                }
            }
            ull o = __shfl_xor_sync(0xffffffffu, bestk, 8);  if (o > bestk) bestk = o;
            o     = __shfl_xor_sync(0xffffffffu, bestk, 16); if (o > bestk) bestk = o;
            if (lane < 8) atomicMax(&sbest[lane & 7], bestk);
            __syncthreads();
            if (tid < BB)
                atomicMax(&g_amax[par * 128 + (bx & 15) * 8 + tid], sbest[tid]);
        }
        gsync(gen, bx);   // doubles as next step's pre-QKV barrier
    } // t

    // final token (decided by step L-1's logits)
    if (bx == 0 && warp < BB && wt) {
        ull key = amax_slot_max((L - 1) & 1, warp, lane);
        if (lane == 0) tok_out[warp * L + (L - 1)] = (float)amax_tok(key);
    }
}

extern "C" void kernel_launch(void* const* d_in, const int* in_sizes, int n_in,
                              void* d_out, int out_size) {
    (void)in_sizes; (void)n_in;
    int L, wt;
    if (out_size % (BB * (VV + 1)) == 0) { L = out_size / (BB * (VV + 1)); wt = 1; }
    else if (out_size % (BB * VV) == 0)  { L = out_size / (BB * VV);       wt = 0; }
    else                                 { L = 48;                         wt = 1; }
    if (L > SMAX - 1) L = SMAX - 1;
    if (L <= 0) return;

    float* out_f = (float*)d_out;
    float* tok_out = out_f;
    float* log_out = wt ? (out_f + (size_t)BB * L) : out_f;

    // opt in to >48KB dynamic shared memory (attribute set, not an allocation)
    cudaFuncSetAttribute(kmain, cudaFuncAttributeMaxDynamicSharedMemorySize, SMEMB);

    kmain<<<NB, NT, SMEMB>>>(
        (const float*)d_in[0],  (const float*)d_in[1],  (const float*)d_in[2],
        (const float*)d_in[3],  (const float*)d_in[4],  (const float*)d_in[5],
        (const float*)d_in[6],  (const float*)d_in[7],  (const float*)d_in[8],
        (const float*)d_in[9],  (const float*)d_in[10], (const float*)d_in[11],
        (const float*)d_in[12], (const float*)d_in[13], (const float*)d_in[14],
        (const float*)d_in[15], (const float*)d_in[16], (const float*)d_in[17],
        (const float*)d_in[18], (const float*)d_in[19], (const float*)d_in[20],
        (const float*)d_in[21], tok_out, log_out, L, wt);
}